// round 7
// baseline (speedup 1.0000x reference)
#include <cuda_runtime.h>
#include <cuda_bf16.h>

// VectorQuantizer forward, single fused kernel:
//   q    = codebook[categories]   (row gather, 512x768 codebook -> L2 resident)
//   out  = q
//   loss = 1.25 * mean((q - inputs)^2)
//
// Loss reduction: one packed 64-bit integer atomicAdd per block.
//   bits [0:52)  : fixed-point (2^20) partial sum accumulator
//   bits [52:64) : block-arrival count
// Integer adds are associative -> bit-deterministic. The atomicAdd's return
// value lets the last block detect completion AND recover the full sum
// without any fence or second pass.
//
// inputs:     [65536, 768] f32
// categories: [65536]      int32
// codebook:   [512, 768]   f32
// out:        65536*768 f32 quantized_st, then 1 f32 loss (if out_size permits)

#define VQ_BS   65536
#define VQ_D    768
#define VQ_D4   192                 // float4s per row
#define VQ_ROWS 32                  // rows per block
#define VQ_NBLK (VQ_BS / VQ_ROWS)   // 2048 blocks

#define VQ_CNT_SHIFT 52
#define VQ_FX_SCALE  1048576.0      // 2^20

__device__ unsigned long long g_vq_acc = 0ULL;   // reset by last block -> replay-idempotent

__global__ __launch_bounds__(VQ_D4) void vq_kernel(
    const float4* __restrict__ in,
    const int* __restrict__ cat,
    const float4* __restrict__ cb,
    float4* __restrict__ out,
    float* __restrict__ loss_out,
    int write_loss)
{
    const int t    = threadIdx.x;             // 0..191 = column (float4)
    const int base = blockIdx.x * VQ_ROWS;

    // Hoist index gather: one 128B read per 96KB payload; removes the per-row
    // cat->cb serial dependency from the hot loop.
    __shared__ int scat[VQ_ROWS];
    if (t < VQ_ROWS) scat[t] = cat[base + t] & 511;   // mask: no-op on valid data
    __syncthreads();

    float s = 0.0f;

    #pragma unroll 4
    for (int r = 0; r < VQ_ROWS; r++) {
        const size_t ib = (size_t)(base + r) * VQ_D4 + t;
        // input: read-once -> evict-first, preserve L2 for codebook
        float4 a = __ldcs(&in[ib]);
        // codebook: hot in L2, default caching
        float4 q = cb[(size_t)scat[r] * VQ_D4 + t];
        // output: write-once, never re-read -> streaming store
        __stcs(&out[ib], q);
        float dx = q.x - a.x;
        float dy = q.y - a.y;
        float dz = q.z - a.z;
        float dw = q.w - a.w;
        s += dx*dx + dy*dy + dz*dz + dw*dw;
    }

    // block reduction: 6 warps of 32
    #pragma unroll
    for (int o = 16; o > 0; o >>= 1)
        s += __shfl_down_sync(0xffffffffu, s, o);

    __shared__ float ws[6];
    if ((t & 31) == 0) ws[t >> 5] = s;
    __syncthreads();

    if (t == 0) {
        float tot = ws[0] + ws[1] + ws[2] + ws[3] + ws[4] + ws[5];
        // fixed-point: ~4.9e4 per block -> ~5.1e10 scaled; total ~1.05e14 < 2^52
        unsigned long long fx = (unsigned long long)((double)tot * VQ_FX_SCALE);
        unsigned long long packed = (1ULL << VQ_CNT_SHIFT) + fx;
        unsigned long long old = atomicAdd(&g_vq_acc, packed);

        if ((old >> VQ_CNT_SHIFT) == (unsigned long long)(VQ_NBLK - 1)) {
            // This block completed the reduction: full sum = old_fx + own fx.
            unsigned long long full = (old + packed) & ((1ULL << VQ_CNT_SHIFT) - 1ULL);
            if (write_loss) {
                const double inv_n = 1.0 / ((double)VQ_BS * (double)VQ_D);
                double mse = ((double)full / VQ_FX_SCALE) * inv_n;
                // loss = (CODEBOOK_COST + COMMITMENT_COST) * mse = 1.25 * mse
                loss_out[(size_t)VQ_BS * VQ_D] = (float)(1.25 * mse);
            }
            g_vq_acc = 0ULL;   // reset for next graph replay (no other block alive)
        }
    }
}

extern "C" void kernel_launch(void* const* d_in, const int* in_sizes, int n_in,
                              void* d_out, int out_size)
{
    const float4* in  = (const float4*)d_in[0];
    const int*    cat = (const int*)d_in[1];
    const float4* cb  = (const float4*)d_in[2];
    float*        out = (float*)d_out;

    const int write_loss = (out_size > VQ_BS * VQ_D) ? 1 : 0;
    vq_kernel<<<VQ_NBLK, VQ_D4>>>(in, cat, cb, (float4*)out, out, write_loss);
}

// round 8
// speedup vs baseline: 1.0064x; 1.0064x over previous
#include <cuda_runtime.h>
#include <cuda_bf16.h>

// VectorQuantizer forward, single fused kernel:
//   q    = codebook[categories]   (row gather, 512x768 codebook -> L2 resident)
//   out  = q
//   loss = 1.25 * mean((q - inputs)^2)
//
// Loss reduction: one packed 64-bit integer atomicAdd per block.
//   bits [0:52)  : fixed-point (2^20) partial sum accumulator
//   bits [52:64) : block-arrival count
// Integer adds are associative -> bit-deterministic. The atomicAdd's return
// value lets the last block detect completion AND recover the full sum
// without any fence or second pass.
//
// NOTE: no __ldcs/__stcs — measured ~2.7us harmful on GB300 here (R5/R7);
// L2 is 126MB so the codebook never needed capacity protection.
//
// inputs:     [65536, 768] f32
// categories: [65536]      int32
// codebook:   [512, 768]   f32
// out:        65536*768 f32 quantized_st, then 1 f32 loss (if out_size permits)

#define VQ_BS   65536
#define VQ_D    768
#define VQ_D4   192                 // float4s per row
#define VQ_ROWS 32                  // rows per block
#define VQ_NBLK (VQ_BS / VQ_ROWS)   // 2048 blocks

#define VQ_CNT_SHIFT 52
#define VQ_FX_SCALE  1048576.0      // 2^20

__device__ unsigned long long g_vq_acc = 0ULL;   // reset by last block -> replay-idempotent

__global__ __launch_bounds__(VQ_D4) void vq_kernel(
    const float4* __restrict__ in,
    const int* __restrict__ cat,
    const float4* __restrict__ cb,
    float4* __restrict__ out,
    float* __restrict__ loss_out,
    int write_loss)
{
    const int t    = threadIdx.x;             // 0..191 = column (float4)
    const int base = blockIdx.x * VQ_ROWS;

    // Hoist index gather: one 128B read per 96KB payload; removes the per-row
    // cat->cb serial dependency from the hot loop.
    __shared__ int scat[VQ_ROWS];
    if (t < VQ_ROWS) scat[t] = cat[base + t] & 511;   // mask: no-op on valid data
    __syncthreads();

    float s = 0.0f;

    #pragma unroll 4
    for (int r = 0; r < VQ_ROWS; r++) {
        const size_t ib = (size_t)(base + r) * VQ_D4 + t;
        float4 a = in[ib];
        float4 q = cb[(size_t)scat[r] * VQ_D4 + t];
        out[ib] = q;
        float dx = q.x - a.x;
        float dy = q.y - a.y;
        float dz = q.z - a.z;
        float dw = q.w - a.w;
        s += dx*dx + dy*dy + dz*dz + dw*dw;
    }

    // block reduction: 6 warps of 32
    #pragma unroll
    for (int o = 16; o > 0; o >>= 1)
        s += __shfl_down_sync(0xffffffffu, s, o);

    __shared__ float ws[6];
    if ((t & 31) == 0) ws[t >> 5] = s;
    __syncthreads();

    if (t == 0) {
        float tot = ws[0] + ws[1] + ws[2] + ws[3] + ws[4] + ws[5];
        // fixed-point: ~4.9e4 per block -> ~5.1e10 scaled; total ~1.05e14 < 2^52
        unsigned long long fx = (unsigned long long)((double)tot * VQ_FX_SCALE);
        unsigned long long packed = (1ULL << VQ_CNT_SHIFT) + fx;
        unsigned long long old = atomicAdd(&g_vq_acc, packed);

        if ((old >> VQ_CNT_SHIFT) == (unsigned long long)(VQ_NBLK - 1)) {
            // This block completed the reduction: full sum = old_fx + own fx.
            unsigned long long full = (old + packed) & ((1ULL << VQ_CNT_SHIFT) - 1ULL);
            if (write_loss) {
                const double inv_n = 1.0 / ((double)VQ_BS * (double)VQ_D);
                double mse = ((double)full / VQ_FX_SCALE) * inv_n;
                // loss = (CODEBOOK_COST + COMMITMENT_COST) * mse = 1.25 * mse
                loss_out[(size_t)VQ_BS * VQ_D] = (float)(1.25 * mse);
            }
            g_vq_acc = 0ULL;   // reset for next graph replay (no other block alive)
        }
    }
}

extern "C" void kernel_launch(void* const* d_in, const int* in_sizes, int n_in,
                              void* d_out, int out_size)
{
    const float4* in  = (const float4*)d_in[0];
    const int*    cat = (const int*)d_in[1];
    const float4* cb  = (const float4*)d_in[2];
    float*        out = (float*)d_out;

    const int write_loss = (out_size > VQ_BS * VQ_D) ? 1 : 0;
    vq_kernel<<<VQ_NBLK, VQ_D4>>>(in, cat, cb, (float4*)out, out, write_loss);
}

// round 9
// speedup vs baseline: 1.0625x; 1.0557x over previous
#include <cuda_runtime.h>
#include <cuda_bf16.h>

// VectorQuantizer forward, single fused kernel (best-measured config = R6):
//   q    = codebook[categories]   (row gather, 512x768 codebook -> L2 resident)
//   out  = q
//   loss = 1.25 * mean((q - inputs)^2)
//
// Loss reduction: one packed 64-bit integer atomicAdd per block.
//   bits [0:52)  : fixed-point (2^20) partial sum accumulator
//   bits [52:64) : block-arrival count
// Integer adds are associative -> bit-deterministic. The atomicAdd's return
// value lets the last block detect completion AND recover the full sum
// without any fence or second pass.
//
// Measured config notes (GB300):
//  - ROWS=16 (4096 blocks): 62.5us mainloop. ROWS=32: 65-69us (tail-wave
//    quantization at 1.4 waves + occupancy drop). Keep 16.
//  - __ldcs/__stcs streaming hints: harmful or neutral here (L2=126MB,
//    codebook never contended). Keep plain LDG/STG.
//  - unroll 8: regs 40, occ 69% -> slower. Keep unroll 4.
//
// inputs:     [65536, 768] f32
// categories: [65536]      int32
// codebook:   [512, 768]   f32
// out:        65536*768 f32 quantized_st, then 1 f32 loss (if out_size permits)

#define VQ_BS   65536
#define VQ_D    768
#define VQ_D4   192                 // float4s per row
#define VQ_ROWS 16                  // rows per block
#define VQ_NBLK (VQ_BS / VQ_ROWS)   // 4096 blocks

#define VQ_CNT_SHIFT 52
#define VQ_FX_SCALE  1048576.0      // 2^20

__device__ unsigned long long g_vq_acc = 0ULL;   // reset by last block -> replay-idempotent

__global__ __launch_bounds__(VQ_D4, 10) void vq_kernel(
    const float4* __restrict__ in,
    const int* __restrict__ cat,
    const float4* __restrict__ cb,
    float4* __restrict__ out,
    float* __restrict__ loss_out,
    int write_loss)
{
    const int t    = threadIdx.x;             // 0..191 = column (float4)
    const int base = blockIdx.x * VQ_ROWS;

    // Hoist index gather: one 64B read per 48KB payload; removes the per-row
    // cat->cb serial dependency from the hot loop.
    __shared__ int scat[VQ_ROWS];
    if (t < VQ_ROWS) scat[t] = cat[base + t] & 511;   // mask: no-op on valid data
    __syncthreads();

    float s = 0.0f;

    #pragma unroll 4
    for (int r = 0; r < VQ_ROWS; r++) {
        const size_t ib = (size_t)(base + r) * VQ_D4 + t;
        float4 a = in[ib];
        float4 q = cb[(size_t)scat[r] * VQ_D4 + t];
        out[ib] = q;
        float dx = q.x - a.x;
        float dy = q.y - a.y;
        float dz = q.z - a.z;
        float dw = q.w - a.w;
        s += dx*dx + dy*dy + dz*dz + dw*dw;
    }

    // block reduction: 6 warps of 32
    #pragma unroll
    for (int o = 16; o > 0; o >>= 1)
        s += __shfl_down_sync(0xffffffffu, s, o);

    __shared__ float ws[6];
    if ((t & 31) == 0) ws[t >> 5] = s;
    __syncthreads();

    if (t == 0) {
        float tot = ws[0] + ws[1] + ws[2] + ws[3] + ws[4] + ws[5];
        // fixed-point: ~2.4e4 per block -> ~2.5e10 scaled; total ~1.05e14 < 2^52
        unsigned long long fx = (unsigned long long)((double)tot * VQ_FX_SCALE);
        unsigned long long packed = (1ULL << VQ_CNT_SHIFT) + fx;
        unsigned long long old = atomicAdd(&g_vq_acc, packed);

        if ((old >> VQ_CNT_SHIFT) == (unsigned long long)(VQ_NBLK - 1)) {
            // This block completed the reduction: full sum = old_fx + own fx.
            unsigned long long full = (old + packed) & ((1ULL << VQ_CNT_SHIFT) - 1ULL);
            if (write_loss) {
                const double inv_n = 1.0 / ((double)VQ_BS * (double)VQ_D);
                double mse = ((double)full / VQ_FX_SCALE) * inv_n;
                // loss = (CODEBOOK_COST + COMMITMENT_COST) * mse = 1.25 * mse
                loss_out[(size_t)VQ_BS * VQ_D] = (float)(1.25 * mse);
            }
            g_vq_acc = 0ULL;   // reset for next graph replay (no other block alive)
        }
    }
}

extern "C" void kernel_launch(void* const* d_in, const int* in_sizes, int n_in,
                              void* d_out, int out_size)
{
    const float4* in  = (const float4*)d_in[0];
    const int*    cat = (const int*)d_in[1];
    const float4* cb  = (const float4*)d_in[2];
    float*        out = (float*)d_out;

    const int write_loss = (out_size > VQ_BS * VQ_D) ? 1 : 0;
    vq_kernel<<<VQ_NBLK, VQ_D4>>>(in, cat, cb, (float4*)out, out, write_loss);
}